// round 10
// baseline (speedup 1.0000x reference)
#include <cuda_runtime.h>
#include <math.h>

// ESN recurrence, GB300 sm_103a.
// Persistent kernel: 128 blocks x 256 threads, 1 CTA/SM.
// W_res in registers as packed f32x2 pairs (fma.rn.f32x2 path).
// Per-step grid sync via 128 distributed flags (release-store pattern),
// polled by warp 0 with one LDG.128 per lane + redux.sync.min.u32 (int redux
// IS supported on sm_103; float redux is not).
// Warp reduction: 9-shuffle select-merge butterfly for 4 accumulators.
// x_{t-1} broadcast through L2 via the out[] rows (__ldcg).
//
// Shapes: input (2048,128) f32, W_in (2048,128) f32, W_res (2048,2048) f32,
// out (2048,2048) f32.  out[t] = erf(U[t] + W_res @ out[t-1]) / sqrt(2048).

#define T_STEPS 2048
#define N_RES   2048
#define D_IN    128
#define G_BLOCKS 128
#define ROWS_PER_BLOCK 16
#define THREADS 256

__device__ unsigned int g_flags[G_BLOCKS];

__global__ void esn_reset_kernel() {
    g_flags[threadIdx.x] = 0u;
}

// ---- Blackwell packed fp32 FMA: d = a*b + c elementwise on (lo,hi) pairs ----
__device__ __forceinline__ unsigned long long ffma2(unsigned long long a,
                                                    unsigned long long b,
                                                    unsigned long long c) {
    unsigned long long d;
    asm("fma.rn.f32x2 %0, %1, %2, %3;" : "=l"(d) : "l"(a), "l"(b), "l"(c));
    return d;
}
__device__ __forceinline__ float f2_lo(unsigned long long v) {
    return __uint_as_float((unsigned)(v & 0xffffffffull));
}
__device__ __forceinline__ float f2_hi(unsigned long long v) {
    return __uint_as_float((unsigned)(v >> 32));
}
__device__ __forceinline__ unsigned redux_min_u32(unsigned v) {
    unsigned r;
    asm("redux.sync.min.u32 %0, %1, 0xffffffff;" : "=r"(r) : "r"(v));
    return r;
}

__global__ void __launch_bounds__(THREADS, 1)
esn_persistent_kernel(const float* __restrict__ input,
                      const float* __restrict__ Win,
                      const float* __restrict__ Wres,
                      float* __restrict__ out)
{
    __shared__ float4 xs4[N_RES / 4];                 // 8 KB: x_{t-1}
    __shared__ float  s_win[ROWS_PER_BLOCK * D_IN];   // 8 KB: W_in slice
    __shared__ float  s_in[D_IN];                     // input row t
    __shared__ float  s_part[ROWS_PER_BLOCK];         // odd-warp partials
    __shared__ float  s_u[ROWS_PER_BLOCK];            // U[t][rows]

    const int tid  = threadIdx.x;
    const int rg   = tid >> 6;     // 0..3  rowgroup (4 rows each)
    const int kc   = tid & 63;     // 0..63 k-chunk of 32
    const int warp = tid >> 5;
    const int lane = tid & 31;
    const int row0 = blockIdx.x * ROWS_PER_BLOCK;

    // ---- one-time: W_in slice to SMEM ----
    for (int i = tid; i < ROWS_PER_BLOCK * D_IN; i += THREADS)
        s_win[i] = Win[row0 * D_IN + i];

    // ---- one-time: W_res tile -> registers as f32x2 pairs, pre-rotated so the
    //      per-step x read xs4[kc*8 + ((q+kc)&7)] is bank-conflict-free. ----
    unsigned long long w2[4][16];
    #pragma unroll
    for (int rr = 0; rr < 4; rr++) {
        const float* wrow = Wres + (size_t)(row0 + rg * 4 + rr) * N_RES + kc * 32;
        #pragma unroll
        for (int q = 0; q < 8; q++) {
            const int qe = (q + kc) & 7;
            const double2 wv = *reinterpret_cast<const double2*>(wrow + qe * 4);
            w2[rr][2 * q]     = __double_as_longlong(wv.x);
            w2[rr][2 * q + 1] = __double_as_longlong(wv.y);
        }
    }
    __syncthreads();

    const float inv_sqrt_n = 0.022097086912079608f;   // 1/sqrt(2048)

    for (int t = 0; t < T_STEPS; t++) {
        // ---- stage input row t (x-independent; overlaps peers finishing t-1) ----
        if (tid < D_IN / 4) {
            float4 v = __ldcg(reinterpret_cast<const float4*>(input + (size_t)t * D_IN) + tid);
            reinterpret_cast<float4*>(s_in)[tid] = v;
        }
        __syncthreads();

        // ---- U[t][row] = dot(input[t], W_in[row]); 16 threads/row ----
        {
            const int row = tid >> 4;
            const int seg = tid & 15;
            float us = 0.f;
            #pragma unroll
            for (int j = 0; j < 8; j++) {
                const int k = seg * 8 + j;
                us += s_in[k] * s_win[row * D_IN + k];
            }
            #pragma unroll
            for (int off = 8; off; off >>= 1)
                us += __shfl_down_sync(0xffffffffu, us, off, 16);
            if (seg == 0) s_u[row] = us;
        }

        // ---- grid barrier: warp 0 polls 128 distributed flags ----
        if (t > 0) {
            if (warp == 0) {
                const uint4* f4 = reinterpret_cast<const uint4*>(g_flags) + lane;
                const unsigned tgt = (unsigned)t;
                while (true) {
                    unsigned a, b, c, d;
                    asm volatile("ld.volatile.global.v4.u32 {%0,%1,%2,%3}, [%4];"
                                 : "=r"(a), "=r"(b), "=r"(c), "=r"(d) : "l"(f4));
                    unsigned m = min(min(a, b), min(c, d));
                    m = redux_min_u32(m);
                    if (m >= tgt) break;
                }
                __threadfence();   // acquire side
            }
            __syncthreads();
            // stage x_{t-1} = out[t-1][:] through L2
            const float4* xprev = reinterpret_cast<const float4*>(out + (size_t)(t - 1) * N_RES);
            xs4[tid]           = __ldcg(xprev + tid);
            xs4[tid + THREADS] = __ldcg(xprev + tid + THREADS);
        }
        __syncthreads();

        // ---- main dot via FFMA2: 4 rows x 32 k per thread, 64 FFMA2 ----
        unsigned long long acc0 = 0ull, acc1 = 0ull, acc2 = 0ull, acc3 = 0ull;
        if (t > 0) {
            const int base = kc * 8;
            #pragma unroll
            for (int q = 0; q < 8; q++) {
                const int idx = base + ((q + kc) & 7);
                const double2 xv = *reinterpret_cast<const double2*>(&xs4[idx]);
                const unsigned long long xa = __double_as_longlong(xv.x);
                const unsigned long long xb = __double_as_longlong(xv.y);
                acc0 = ffma2(w2[0][2 * q], xa, acc0);
                acc0 = ffma2(w2[0][2 * q + 1], xb, acc0);
                acc1 = ffma2(w2[1][2 * q], xa, acc1);
                acc1 = ffma2(w2[1][2 * q + 1], xb, acc1);
                acc2 = ffma2(w2[2][2 * q], xa, acc2);
                acc2 = ffma2(w2[2][2 * q + 1], xb, acc2);
                acc3 = ffma2(w2[3][2 * q], xa, acc3);
                acc3 = ffma2(w2[3][2 * q + 1], xb, acc3);
            }
        }

        // ---- 9-shuffle select-merge reduction of 4 accs across 32 lanes ----
        // Level 16 on each acc, then merge pairs by lane bit4; level 8, merge by
        // bit3; levels 4/2/1 on the single merged value. Row results land at:
        //   lane 0 -> row rg*4+0, lane 16 -> +1, lane 8 -> +2, lane 24 -> +3.
        float a0 = f2_lo(acc0) + f2_hi(acc0);
        float a1 = f2_lo(acc1) + f2_hi(acc1);
        float a2 = f2_lo(acc2) + f2_hi(acc2);
        float a3 = f2_lo(acc3) + f2_hi(acc3);

        a0 += __shfl_xor_sync(0xffffffffu, a0, 16);
        a1 += __shfl_xor_sync(0xffffffffu, a1, 16);
        a2 += __shfl_xor_sync(0xffffffffu, a2, 16);
        a3 += __shfl_xor_sync(0xffffffffu, a3, 16);

        float e = (lane & 16) ? a1 : a0;   // rows +0 / +1
        float f = (lane & 16) ? a3 : a2;   // rows +2 / +3
        e += __shfl_xor_sync(0xffffffffu, e, 8);
        f += __shfl_xor_sync(0xffffffffu, f, 8);

        float g = (lane & 8) ? f : e;      // quadrant-of-8 owns one row
        g += __shfl_xor_sync(0xffffffffu, g, 4);
        g += __shfl_xor_sync(0xffffffffu, g, 2);
        g += __shfl_xor_sync(0xffffffffu, g, 1);

        const bool owner = ((lane & 7) == 0);               // lanes 0,8,16,24
        const int  row   = rg * 4 + ((lane >> 4) & 1) + ((lane >> 2) & 2);

        // odd warp of each rowgroup publishes its 4 partials (k upper half)
        if ((warp & 1) && owner) s_part[row] = g;
        __syncthreads();

        // even warp: combine halves, add U, erf, store (4 lanes in parallel)
        if (!(warp & 1) && owner) {
            const float pre = s_u[row] + g + s_part[row];
            out[(size_t)t * N_RES + row0 + row] = erff(pre) * inv_sqrt_n;
        }
        __syncthreads();

        // ---- publish step completion: fence + own flag (no atomics) ----
        if (tid == 0) {
            __threadfence();
            *(volatile unsigned int*)&g_flags[blockIdx.x] = (unsigned)(t + 1);
        }
    }
}

extern "C" void kernel_launch(void* const* d_in, const int* in_sizes, int n_in,
                              void* d_out, int out_size)
{
    const float* input = (const float*)d_in[0];   // (2048, 128)
    const float* Win   = (const float*)d_in[1];   // (2048, 128)
    const float* Wres  = (const float*)d_in[2];   // (2048, 2048)
    float* out = (float*)d_out;                   // (2048, 2048)

    esn_reset_kernel<<<1, G_BLOCKS>>>();
    esn_persistent_kernel<<<G_BLOCKS, THREADS>>>(input, Win, Wres, out);
}